// round 1
// baseline (speedup 1.0000x reference)
#include <cuda_runtime.h>
#include <cuda_bf16.h>

#define N_NODES 50000
#define E_EDGES 800000
#define D 128
#define KDIM 512   // effective concat width after folding t into r

// Scratch (allocation-free rule: __device__ globals)
__device__ float g_agg[(size_t)N_NODES * 3 * D];   // [node][p][feat], 76.8 MB
__device__ float g_Weff[D * KDIM];                  // 256 KB

// ---------------------------------------------------------------------------
// Fold W[:,512:640] (t-direction, which reuses positions==0) into W[:,128:256]
// ---------------------------------------------------------------------------
__global__ void weff_kernel(const float* __restrict__ W) {
    int i = blockIdx.x * blockDim.x + threadIdx.x;
    if (i >= D * KDIM) return;
    int j = i / KDIM;          // out feature
    int c = i % KDIM;          // concat column
    float v = W[j * 640 + c];
    if (c >= 128 && c < 256) v += W[j * 640 + c + 384];  // + t block
    g_Weff[i] = v;
}

// ---------------------------------------------------------------------------
// Edge aggregation: one warp per edge, float4 per lane, atomic scatter.
// positions==3 contributes to no direction -> skipped entirely.
// ---------------------------------------------------------------------------
__global__ void edge_kernel(const float4* __restrict__ h4,
                            const float* __restrict__ dist,
                            const int* __restrict__ src,
                            const int* __restrict__ dst,
                            const int* __restrict__ pos) {
    int idx = blockIdx.x * blockDim.x + threadIdx.x;
    int e = idx >> 5;
    int lane = idx & 31;
    if (e >= E_EDGES) return;
    int p = pos[e];
    if (p >= 3) return;
    float w = dist[e];
    int s = src[e];
    int d = dst[e];
    float4 hv = h4[(size_t)s * 32 + lane];
    float* o = g_agg + ((size_t)d * 3 + p) * D + lane * 4;
    atomicAdd(o + 0, hv.x * w);
    atomicAdd(o + 1, hv.y * w);
    atomicAdd(o + 2, hv.z * w);
    atomicAdd(o + 3, hv.w * w);
}

// ---------------------------------------------------------------------------
// Fused GEMM (X[50000x512] @ Weff^T[512x128]) + bias + LayerNorm + ReLU
// BM=64 nodes, BN=128 outs, BK=32. 256 threads, 8x4 per-thread tile.
// ---------------------------------------------------------------------------
__global__ __launch_bounds__(256) void gemm_ln_kernel(
    const float* __restrict__ h,
    const float* __restrict__ b,
    const float* __restrict__ gamma,
    const float* __restrict__ beta,
    float* __restrict__ out) {

    __shared__ float sm[64 * 128];            // 32 KB, unioned: tiles then zbuf
    float (*Xs)[65]  = (float(*)[65])sm;      // [32][65]  = 2080 floats
    float (*Ws)[129] = (float(*)[129])(sm + 2080);  // [32][129] = 4128 floats

    const int tid = threadIdx.x;
    const int tx = tid & 31;                  // output-col lane
    const int ty = tid >> 5;                  // node-group / warp id (0..7)
    const int nodeBase = blockIdx.x * 64;

    float acc[8][4];
#pragma unroll
    for (int i = 0; i < 8; i++)
#pragma unroll
        for (int j = 0; j < 4; j++) acc[i][j] = 0.f;

    for (int k0 = 0; k0 < KDIM; k0 += 32) {
        // X tile -> Xs[k][node] (transposed, padded)
#pragma unroll
        for (int it = 0; it < 8; it++) {
            int i = it * 256 + tid;
            int node = i >> 5;
            int kk = i & 31;
            int gn = nodeBase + node;
            int c = k0 + kk;
            float v = 0.f;
            if (gn < N_NODES) {
                v = (c < 128) ? h[(size_t)gn * 128 + c]
                              : g_agg[(size_t)gn * 384 + (c - 128)];
            }
            Xs[kk][node] = v;
        }
        // W tile -> Ws[k][col] (transposed, padded)
#pragma unroll
        for (int it = 0; it < 16; it++) {
            int i = it * 256 + tid;
            int col = i >> 5;
            int kk = i & 31;
            Ws[kk][col] = g_Weff[col * KDIM + k0 + kk];
        }
        __syncthreads();

#pragma unroll
        for (int kk = 0; kk < 32; kk++) {
            float a[8], w[4];
#pragma unroll
            for (int i = 0; i < 8; i++) a[i] = Xs[kk][ty * 8 + i];   // broadcast
#pragma unroll
            for (int j = 0; j < 4; j++) w[j] = Ws[kk][tx + 32 * j];  // conflict-free
#pragma unroll
            for (int i = 0; i < 8; i++)
#pragma unroll
                for (int j = 0; j < 4; j++)
                    acc[i][j] += a[i] * w[j];
        }
        __syncthreads();
    }

    // z (+bias) into smem zbuf [64][128]
#pragma unroll
    for (int i = 0; i < 8; i++)
#pragma unroll
        for (int j = 0; j < 4; j++) {
            int col = tx + 32 * j;
            sm[(ty * 8 + i) * 128 + col] = acc[i][j] + b[col];
        }
    __syncthreads();

    // LayerNorm + ReLU: warp ty handles nodes ty*8 .. ty*8+7
    float4 g4 = ((const float4*)gamma)[tx];
    float4 b4 = ((const float4*)beta)[tx];
#pragma unroll
    for (int i = 0; i < 8; i++) {
        int node = ty * 8 + i;
        int gn = nodeBase + node;
        if (gn >= N_NODES) continue;   // uniform across warp
        float4 v = ((const float4*)(sm + node * 128))[tx];
        float s1 = v.x + v.y + v.z + v.w;
        float s2 = v.x * v.x + v.y * v.y + v.z * v.z + v.w * v.w;
#pragma unroll
        for (int off = 16; off > 0; off >>= 1) {
            s1 += __shfl_xor_sync(0xFFFFFFFF, s1, off);
            s2 += __shfl_xor_sync(0xFFFFFFFF, s2, off);
        }
        float mu = s1 * (1.0f / 128.0f);
        float var = s2 * (1.0f / 128.0f) - mu * mu;
        float rs = rsqrtf(var + 1e-5f);
        float4 o;
        o.x = fmaxf((v.x - mu) * rs * g4.x + b4.x, 0.f);
        o.y = fmaxf((v.y - mu) * rs * g4.y + b4.y, 0.f);
        o.z = fmaxf((v.z - mu) * rs * g4.z + b4.z, 0.f);
        o.w = fmaxf((v.w - mu) * rs * g4.w + b4.w, 0.f);
        ((float4*)(out + (size_t)gn * 128))[tx] = o;
    }
}

extern "C" void kernel_launch(void* const* d_in, const int* in_sizes, int n_in,
                              void* d_out, int out_size) {
    const float* h     = (const float*)d_in[0];
    const float* dist  = (const float*)d_in[1];
    const float* W     = (const float*)d_in[2];
    const float* b     = (const float*)d_in[3];
    const float* gamma = (const float*)d_in[4];
    const float* beta  = (const float*)d_in[5];
    const int* src     = (const int*)d_in[6];
    const int* dst     = (const int*)d_in[7];
    const int* pos     = (const int*)d_in[8];
    float* out = (float*)d_out;

    void* aggp = nullptr;
    cudaGetSymbolAddress(&aggp, g_agg);
    cudaMemsetAsync(aggp, 0, (size_t)N_NODES * 3 * D * sizeof(float));

    weff_kernel<<<(D * KDIM + 255) / 256, 256>>>(W);

    long long ethreads = (long long)E_EDGES * 32;
    edge_kernel<<<(int)((ethreads + 255) / 256), 256>>>(
        (const float4*)h, dist, src, dst, pos);

    gemm_ln_kernel<<<(N_NODES + 63) / 64, 256>>>(h, b, gamma, beta, out);
}

// round 2
// speedup vs baseline: 1.1183x; 1.1183x over previous
#include <cuda_runtime.h>
#include <cuda_bf16.h>

#define N_NODES 50000
#define E_EDGES 800000
#define D 128
#define KDIM 512   // effective concat width after folding t into r

// Scratch (allocation-free rule: __device__ globals)
__device__ float g_agg[(size_t)N_NODES * 3 * D];   // [node][p][feat], 76.8 MB
__device__ float g_Weff[D * KDIM];                  // 256 KB

// ---------------------------------------------------------------------------
// Fold W[:,512:640] (t-direction, which reuses positions==0) into W[:,128:256]
// ---------------------------------------------------------------------------
__global__ void weff_kernel(const float* __restrict__ W) {
    int i = blockIdx.x * blockDim.x + threadIdx.x;
    if (i >= D * KDIM) return;
    int j = i / KDIM;          // out feature
    int c = i % KDIM;          // concat column
    float v = W[j * 640 + c];
    if (c >= 128 && c < 256) v += W[j * 640 + c + 384];  // + t block
    g_Weff[i] = v;
}

// ---------------------------------------------------------------------------
// Edge aggregation: one warp per edge, float4 per lane, ONE red.global.v4.f32
// per lane (sm_90+ vector fp32 reduction) instead of 4 scalar atomics.
// positions==3 contributes to no direction -> skipped entirely.
// ---------------------------------------------------------------------------
__device__ __forceinline__ void red_add_v4(float* p, float4 v) {
    asm volatile("red.global.add.v4.f32 [%0], {%1, %2, %3, %4};"
                 :: "l"(p), "f"(v.x), "f"(v.y), "f"(v.z), "f"(v.w)
                 : "memory");
}

__global__ void edge_kernel(const float4* __restrict__ h4,
                            const float* __restrict__ dist,
                            const int* __restrict__ src,
                            const int* __restrict__ dst,
                            const int* __restrict__ pos) {
    int idx = blockIdx.x * blockDim.x + threadIdx.x;
    int e = idx >> 5;
    int lane = idx & 31;
    if (e >= E_EDGES) return;
    int p = pos[e];
    if (p >= 3) return;
    float w = dist[e];
    int s = src[e];
    int d = dst[e];
    float4 hv = h4[(size_t)s * 32 + lane];
    float4 c;
    c.x = hv.x * w; c.y = hv.y * w; c.z = hv.z * w; c.w = hv.w * w;
    float* o = g_agg + ((size_t)d * 3 + p) * D + lane * 4;
    red_add_v4(o, c);
}

// ---------------------------------------------------------------------------
// Fused GEMM (X[50000x512] @ Weff^T[512x128]) + bias + LayerNorm + ReLU
// BM=64 nodes, BN=128 outs, BK=32. 256 threads, 8x4 per-thread tile.
// ---------------------------------------------------------------------------
__global__ __launch_bounds__(256) void gemm_ln_kernel(
    const float* __restrict__ h,
    const float* __restrict__ b,
    const float* __restrict__ gamma,
    const float* __restrict__ beta,
    float* __restrict__ out) {

    __shared__ float sm[64 * 128];            // 32 KB, unioned: tiles then zbuf
    float (*Xs)[65]  = (float(*)[65])sm;      // [32][65]  = 2080 floats
    float (*Ws)[129] = (float(*)[129])(sm + 2080);  // [32][129] = 4128 floats

    const int tid = threadIdx.x;
    const int tx = tid & 31;                  // output-col lane
    const int ty = tid >> 5;                  // node-group / warp id (0..7)
    const int nodeBase = blockIdx.x * 64;

    float acc[8][4];
#pragma unroll
    for (int i = 0; i < 8; i++)
#pragma unroll
        for (int j = 0; j < 4; j++) acc[i][j] = 0.f;

    for (int k0 = 0; k0 < KDIM; k0 += 32) {
        // X tile -> Xs[k][node] (transposed, padded)
#pragma unroll
        for (int it = 0; it < 8; it++) {
            int i = it * 256 + tid;
            int node = i >> 5;
            int kk = i & 31;
            int gn = nodeBase + node;
            int c = k0 + kk;
            float v = 0.f;
            if (gn < N_NODES) {
                v = (c < 128) ? h[(size_t)gn * 128 + c]
                              : g_agg[(size_t)gn * 384 + (c - 128)];
            }
            Xs[kk][node] = v;
        }
        // W tile -> Ws[k][col] (transposed, padded)
#pragma unroll
        for (int it = 0; it < 16; it++) {
            int i = it * 256 + tid;
            int col = i >> 5;
            int kk = i & 31;
            Ws[kk][col] = g_Weff[col * KDIM + k0 + kk];
        }
        __syncthreads();

#pragma unroll
        for (int kk = 0; kk < 32; kk++) {
            float a[8], w[4];
#pragma unroll
            for (int i = 0; i < 8; i++) a[i] = Xs[kk][ty * 8 + i];   // broadcast
#pragma unroll
            for (int j = 0; j < 4; j++) w[j] = Ws[kk][tx + 32 * j];  // conflict-free
#pragma unroll
            for (int i = 0; i < 8; i++)
#pragma unroll
                for (int j = 0; j < 4; j++)
                    acc[i][j] += a[i] * w[j];
        }
        __syncthreads();
    }

    // z (+bias) into smem zbuf [64][128]
#pragma unroll
    for (int i = 0; i < 8; i++)
#pragma unroll
        for (int j = 0; j < 4; j++) {
            int col = tx + 32 * j;
            sm[(ty * 8 + i) * 128 + col] = acc[i][j] + b[col];
        }
    __syncthreads();

    // LayerNorm + ReLU: warp ty handles nodes ty*8 .. ty*8+7
    float4 g4 = ((const float4*)gamma)[tx];
    float4 b4 = ((const float4*)beta)[tx];
#pragma unroll
    for (int i = 0; i < 8; i++) {
        int node = ty * 8 + i;
        int gn = nodeBase + node;
        if (gn >= N_NODES) continue;   // uniform across warp
        float4 v = ((const float4*)(sm + node * 128))[tx];
        float s1 = v.x + v.y + v.z + v.w;
        float s2 = v.x * v.x + v.y * v.y + v.z * v.z + v.w * v.w;
#pragma unroll
        for (int off = 16; off > 0; off >>= 1) {
            s1 += __shfl_xor_sync(0xFFFFFFFF, s1, off);
            s2 += __shfl_xor_sync(0xFFFFFFFF, s2, off);
        }
        float mu = s1 * (1.0f / 128.0f);
        float var = s2 * (1.0f / 128.0f) - mu * mu;
        float rs = rsqrtf(var + 1e-5f);
        float4 o;
        o.x = fmaxf((v.x - mu) * rs * g4.x + b4.x, 0.f);
        o.y = fmaxf((v.y - mu) * rs * g4.y + b4.y, 0.f);
        o.z = fmaxf((v.z - mu) * rs * g4.z + b4.z, 0.f);
        o.w = fmaxf((v.w - mu) * rs * g4.w + b4.w, 0.f);
        ((float4*)(out + (size_t)gn * 128))[tx] = o;
    }
}

extern "C" void kernel_launch(void* const* d_in, const int* in_sizes, int n_in,
                              void* d_out, int out_size) {
    const float* h     = (const float*)d_in[0];
    const float* dist  = (const float*)d_in[1];
    const float* W     = (const float*)d_in[2];
    const float* b     = (const float*)d_in[3];
    const float* gamma = (const float*)d_in[4];
    const float* beta  = (const float*)d_in[5];
    const int* src     = (const int*)d_in[6];
    const int* dst     = (const int*)d_in[7];
    const int* pos     = (const int*)d_in[8];
    float* out = (float*)d_out;

    void* aggp = nullptr;
    cudaGetSymbolAddress(&aggp, g_agg);
    cudaMemsetAsync(aggp, 0, (size_t)N_NODES * 3 * D * sizeof(float));

    weff_kernel<<<(D * KDIM + 255) / 256, 256>>>(W);

    long long ethreads = (long long)E_EDGES * 32;
    edge_kernel<<<(int)((ethreads + 255) / 256), 256>>>(
        (const float4*)h, dist, src, dst, pos);

    gemm_ln_kernel<<<(N_NODES + 63) / 64, 256>>>(h, b, gamma, beta, out);
}

// round 3
// speedup vs baseline: 1.2922x; 1.1555x over previous
#include <cuda_runtime.h>
#include <cuda_bf16.h>

#define N_NODES 50000
#define E_EDGES 800000
#define D 128
#define KDIM 512   // effective concat width after folding t into r
#define CAP 96     // per-dst bucket capacity (Poisson(16) edges/dst; +overflow path)
#define OVF_CAP 4096

// Scratch (allocation-free rule: __device__ globals)
__device__ float g_agg[(size_t)N_NODES * 3 * D];            // 76.8 MB
__device__ float g_Weff[D * KDIM];                          // 256 KB
__device__ unsigned long long g_rec[(size_t)N_NODES * CAP]; // 38.4 MB
__device__ int g_count[N_NODES];
__device__ int g_novf;
__device__ int4 g_ovf[OVF_CAP];

// ---------------------------------------------------------------------------
// Fold W[:,512:640] (t reuses positions==0) into W[:,128:256]
// ---------------------------------------------------------------------------
__global__ void weff_kernel(const float* __restrict__ W) {
    int i = blockIdx.x * blockDim.x + threadIdx.x;
    if (i >= D * KDIM) return;
    int j = i / KDIM;
    int c = i % KDIM;
    float v = W[j * 640 + c];
    if (c >= 128 && c < 256) v += W[j * 640 + c + 384];
    g_Weff[i] = v;
}

// ---------------------------------------------------------------------------
// Bucket contributing edges by dst. Record = (src | p<<16, f32 w) packed u64.
// ---------------------------------------------------------------------------
__global__ void fill_kernel(const float* __restrict__ dist,
                            const int* __restrict__ src,
                            const int* __restrict__ dst,
                            const int* __restrict__ pos) {
    int e = blockIdx.x * blockDim.x + threadIdx.x;
    if (e >= E_EDGES) return;
    int p = pos[e];
    if (p >= 3) return;
    int d = dst[e];
    int s = src[e];
    float w = dist[e];
    int slot = atomicAdd(&g_count[d], 1);
    if (slot < CAP) {
        unsigned lo = (unsigned)s | ((unsigned)p << 16);
        unsigned hi = __float_as_uint(w);
        g_rec[(size_t)d * CAP + slot] = (unsigned long long)lo |
                                        ((unsigned long long)hi << 32);
    } else {
        int o = atomicAdd(&g_novf, 1);
        if (o < OVF_CAP) g_ovf[o] = make_int4(s, d, p, __float_as_int(w));
    }
}

// ---------------------------------------------------------------------------
// Aggregation: one warp per dst node, 3 direction channels in registers,
// plain stores to g_agg (no atomics, no prior memset needed).
// ---------------------------------------------------------------------------
__global__ __launch_bounds__(256) void agg_kernel(const float4* __restrict__ h4) {
    int idx = blockIdx.x * blockDim.x + threadIdx.x;
    int d = idx >> 5;
    int lane = idx & 31;
    if (d >= N_NODES) return;
    int deg = g_count[d];
    if (deg > CAP) deg = CAP;
    float4 a0 = {0.f, 0.f, 0.f, 0.f};
    float4 a1 = {0.f, 0.f, 0.f, 0.f};
    float4 a2 = {0.f, 0.f, 0.f, 0.f};
    const unsigned long long* rp = g_rec + (size_t)d * CAP;
#pragma unroll 4
    for (int i = 0; i < deg; i++) {
        unsigned long long rec = __ldg(rp + i);
        unsigned lo = (unsigned)rec;
        float w = __uint_as_float((unsigned)(rec >> 32));
        int s = lo & 0xFFFF;
        int p = lo >> 16;
        float4 hv = h4[(size_t)s * 32 + lane];
        float4 c = {hv.x * w, hv.y * w, hv.z * w, hv.w * w};
        if (p == 0)      { a0.x += c.x; a0.y += c.y; a0.z += c.z; a0.w += c.w; }
        else if (p == 1) { a1.x += c.x; a1.y += c.y; a1.z += c.z; a1.w += c.w; }
        else             { a2.x += c.x; a2.y += c.y; a2.z += c.z; a2.w += c.w; }
    }
    float4* o = (float4*)(g_agg + (size_t)d * 384);
    o[lane] = a0;
    o[32 + lane] = a1;
    o[64 + lane] = a2;
}

// ---------------------------------------------------------------------------
// Overflow fixup (normally zero work): vector RED into g_agg AFTER agg stores.
// ---------------------------------------------------------------------------
__device__ __forceinline__ void red_add_v4(float* p, float4 v) {
    asm volatile("red.global.add.v4.f32 [%0], {%1, %2, %3, %4};"
                 :: "l"(p), "f"(v.x), "f"(v.y), "f"(v.z), "f"(v.w)
                 : "memory");
}

__global__ void fixup_kernel(const float4* __restrict__ h4) {
    int n = g_novf;
    if (n > OVF_CAP) n = OVF_CAP;
    int warp = (blockIdx.x * blockDim.x + threadIdx.x) >> 5;
    int lane = threadIdx.x & 31;
    int nwarps = (gridDim.x * blockDim.x) >> 5;
    for (int i = warp; i < n; i += nwarps) {
        int4 r = g_ovf[i];
        float w = __int_as_float(r.w);
        float4 hv = h4[(size_t)r.x * 32 + lane];
        float4 c = {hv.x * w, hv.y * w, hv.z * w, hv.w * w};
        float* o = g_agg + ((size_t)r.y * 3 + r.z) * D + lane * 4;
        red_add_v4(o, c);
    }
}

// ---------------------------------------------------------------------------
// Fused GEMM (X[50000x512] @ Weff^T[512x128]) + bias + LayerNorm + ReLU.
// BM=64, BN=128, BK=32, 256 threads. Per-thread 8 rows x 4 contiguous cols.
// LN done entirely in registers via warp shfl (no smem z round-trip).
// ---------------------------------------------------------------------------
__global__ __launch_bounds__(256) void gemm_ln_kernel(
    const float* __restrict__ h,
    const float* __restrict__ b,
    const float* __restrict__ gamma,
    const float* __restrict__ beta,
    float* __restrict__ out) {

    __shared__ float Xs[32][65];    // [k][node]
    __shared__ float Ws[32][132];   // [k][col], row stride 528B (16B aligned)

    const int tid = threadIdx.x;
    const int tx = tid & 31;        // lane: cols 4tx..4tx+3
    const int ty = tid >> 5;        // warp: rows ty*8..ty*8+7
    const int nodeBase = blockIdx.x * 64;

    float acc[8][4];
#pragma unroll
    for (int i = 0; i < 8; i++)
#pragma unroll
        for (int j = 0; j < 4; j++) acc[i][j] = 0.f;

    for (int k0 = 0; k0 < KDIM; k0 += 32) {
#pragma unroll
        for (int it = 0; it < 8; it++) {
            int i = it * 256 + tid;
            int node = i >> 5;
            int kk = i & 31;
            int gn = nodeBase + node;
            int c = k0 + kk;
            float v = 0.f;
            if (gn < N_NODES) {
                v = (c < 128) ? h[(size_t)gn * 128 + c]
                              : g_agg[(size_t)gn * 384 + (c - 128)];
            }
            Xs[kk][node] = v;
        }
#pragma unroll
        for (int it = 0; it < 16; it++) {
            int i = it * 256 + tid;
            int col = i >> 5;
            int kk = i & 31;
            Ws[kk][col] = g_Weff[col * KDIM + k0 + kk];
        }
        __syncthreads();

#pragma unroll
        for (int kk = 0; kk < 32; kk++) {
            float4 w4 = *(const float4*)&Ws[kk][tx * 4];
            float a[8];
#pragma unroll
            for (int i = 0; i < 8; i++) a[i] = Xs[kk][ty * 8 + i];
#pragma unroll
            for (int i = 0; i < 8; i++) {
                acc[i][0] += a[i] * w4.x;
                acc[i][1] += a[i] * w4.y;
                acc[i][2] += a[i] * w4.z;
                acc[i][3] += a[i] * w4.w;
            }
        }
        __syncthreads();
    }

    // Bias + LayerNorm + ReLU fully in registers (row lives in one warp).
    float4 bb = ((const float4*)b)[tx];
    float4 g4 = ((const float4*)gamma)[tx];
    float4 be = ((const float4*)beta)[tx];
#pragma unroll
    for (int i = 0; i < 8; i++) {
        int gn = nodeBase + ty * 8 + i;
        if (gn >= N_NODES) continue;   // uniform across warp
        float4 v;
        v.x = acc[i][0] + bb.x;
        v.y = acc[i][1] + bb.y;
        v.z = acc[i][2] + bb.z;
        v.w = acc[i][3] + bb.w;
        float s1 = v.x + v.y + v.z + v.w;
        float s2 = v.x * v.x + v.y * v.y + v.z * v.z + v.w * v.w;
#pragma unroll
        for (int off = 16; off > 0; off >>= 1) {
            s1 += __shfl_xor_sync(0xFFFFFFFF, s1, off);
            s2 += __shfl_xor_sync(0xFFFFFFFF, s2, off);
        }
        float mu = s1 * (1.0f / 128.0f);
        float var = s2 * (1.0f / 128.0f) - mu * mu;
        float rs = rsqrtf(var + 1e-5f);
        float4 o;
        o.x = fmaxf((v.x - mu) * rs * g4.x + be.x, 0.f);
        o.y = fmaxf((v.y - mu) * rs * g4.y + be.y, 0.f);
        o.z = fmaxf((v.z - mu) * rs * g4.z + be.z, 0.f);
        o.w = fmaxf((v.w - mu) * rs * g4.w + be.w, 0.f);
        ((float4*)(out + (size_t)gn * 128))[tx] = o;
    }
}

extern "C" void kernel_launch(void* const* d_in, const int* in_sizes, int n_in,
                              void* d_out, int out_size) {
    const float* h     = (const float*)d_in[0];
    const float* dist  = (const float*)d_in[1];
    const float* W     = (const float*)d_in[2];
    const float* b     = (const float*)d_in[3];
    const float* gamma = (const float*)d_in[4];
    const float* beta  = (const float*)d_in[5];
    const int* src     = (const int*)d_in[6];
    const int* dst     = (const int*)d_in[7];
    const int* pos     = (const int*)d_in[8];
    float* out = (float*)d_out;

    void* cntp = nullptr; cudaGetSymbolAddress(&cntp, g_count);
    void* novp = nullptr; cudaGetSymbolAddress(&novp, g_novf);
    cudaMemsetAsync(cntp, 0, N_NODES * sizeof(int));
    cudaMemsetAsync(novp, 0, sizeof(int));

    weff_kernel<<<(D * KDIM + 255) / 256, 256>>>(W);

    fill_kernel<<<(E_EDGES + 255) / 256, 256>>>(dist, src, dst, pos);

    agg_kernel<<<(N_NODES * 32 + 255) / 256, 256>>>((const float4*)h);

    fixup_kernel<<<8, 256>>>((const float4*)h);

    gemm_ln_kernel<<<(N_NODES + 63) / 64, 256>>>(h, b, gamma, beta, out);
}

// round 4
// speedup vs baseline: 1.3896x; 1.0754x over previous
#include <cuda_runtime.h>
#include <cuda_bf16.h>

#define N_NODES 50000
#define E_EDGES 800000
#define D 128
#define KDIM 512   // effective concat width after folding t into r
#define CAP 96     // per-dst bucket capacity (Poisson(16) edges/dst; +overflow path)
#define OVF_CAP 4096

typedef unsigned long long u64;

// Scratch (allocation-free rule: __device__ globals)
__device__ float g_agg[(size_t)N_NODES * 3 * D];            // 76.8 MB
__device__ float g_Weff[KDIM * D];                          // 256 KB, [k][col]
__device__ u64 g_rec[(size_t)N_NODES * CAP];                // 38.4 MB
__device__ int g_count[N_NODES];
__device__ int g_novf;
__device__ int4 g_ovf[OVF_CAP];

__device__ __forceinline__ u64 fma_f32x2(u64 a, u64 b, u64 c) {
    u64 d;
    asm("fma.rn.f32x2 %0, %1, %2, %3;" : "=l"(d) : "l"(a), "l"(b), "l"(c));
    return d;
}
__device__ __forceinline__ u64 dup_f32(float w) {
    u64 d;
    asm("mov.b64 %0, {%1, %1};" : "=l"(d) : "f"(w));
    return d;
}

// ---------------------------------------------------------------------------
// Fold W[:,512:640] (t reuses positions==0) into W[:,128:256]; store TRANSPOSED
// as [k][col] so the GEMM W-tile load is coalesced.
// ---------------------------------------------------------------------------
__global__ void weff_kernel(const float* __restrict__ W) {
    int i = blockIdx.x * blockDim.x + threadIdx.x;
    if (i >= D * KDIM) return;
    int j = i / KDIM;          // out feature
    int c = i % KDIM;          // concat column
    float v = W[j * 640 + c];
    if (c >= 128 && c < 256) v += W[j * 640 + c + 384];
    g_Weff[c * D + j] = v;
}

// ---------------------------------------------------------------------------
// Bucket contributing edges by dst. Record = (src | p<<16, f32 w) packed u64.
// ---------------------------------------------------------------------------
__global__ void fill_kernel(const float* __restrict__ dist,
                            const int* __restrict__ src,
                            const int* __restrict__ dst,
                            const int* __restrict__ pos) {
    int e = blockIdx.x * blockDim.x + threadIdx.x;
    if (e >= E_EDGES) return;
    int p = pos[e];
    if (p >= 3) return;
    int d = dst[e];
    int s = src[e];
    float w = dist[e];
    int slot = atomicAdd(&g_count[d], 1);
    if (slot < CAP) {
        unsigned lo = (unsigned)s | ((unsigned)p << 16);
        unsigned hi = __float_as_uint(w);
        g_rec[(size_t)d * CAP + slot] = (u64)lo | ((u64)hi << 32);
    } else {
        int o = atomicAdd(&g_novf, 1);
        if (o < OVF_CAP) g_ovf[o] = make_int4(s, d, p, __float_as_int(w));
    }
}

// ---------------------------------------------------------------------------
// Aggregation: one warp per dst node, 3 direction channels in registers,
// plain stores to g_agg (no atomics, no prior memset needed).
// ---------------------------------------------------------------------------
__global__ __launch_bounds__(256) void agg_kernel(const float4* __restrict__ h4) {
    int idx = blockIdx.x * blockDim.x + threadIdx.x;
    int d = idx >> 5;
    int lane = idx & 31;
    if (d >= N_NODES) return;
    int deg = g_count[d];
    if (deg > CAP) deg = CAP;
    float4 a0 = {0.f, 0.f, 0.f, 0.f};
    float4 a1 = {0.f, 0.f, 0.f, 0.f};
    float4 a2 = {0.f, 0.f, 0.f, 0.f};
    const u64* rp = g_rec + (size_t)d * CAP;
#pragma unroll 4
    for (int i = 0; i < deg; i++) {
        u64 rec = __ldg(rp + i);
        unsigned lo = (unsigned)rec;
        float w = __uint_as_float((unsigned)(rec >> 32));
        int s = lo & 0xFFFF;
        int p = lo >> 16;
        float4 hv = h4[(size_t)s * 32 + lane];
        float4 c = {hv.x * w, hv.y * w, hv.z * w, hv.w * w};
        if (p == 0)      { a0.x += c.x; a0.y += c.y; a0.z += c.z; a0.w += c.w; }
        else if (p == 1) { a1.x += c.x; a1.y += c.y; a1.z += c.z; a1.w += c.w; }
        else             { a2.x += c.x; a2.y += c.y; a2.z += c.z; a2.w += c.w; }
    }
    float4* o = (float4*)(g_agg + (size_t)d * 384);
    o[lane] = a0;
    o[32 + lane] = a1;
    o[64 + lane] = a2;
}

// ---------------------------------------------------------------------------
// Overflow fixup (normally zero work): vector RED into g_agg AFTER agg stores.
// ---------------------------------------------------------------------------
__device__ __forceinline__ void red_add_v4(float* p, float4 v) {
    asm volatile("red.global.add.v4.f32 [%0], {%1, %2, %3, %4};"
                 :: "l"(p), "f"(v.x), "f"(v.y), "f"(v.z), "f"(v.w)
                 : "memory");
}

__global__ void fixup_kernel(const float4* __restrict__ h4) {
    int n = g_novf;
    if (n > OVF_CAP) n = OVF_CAP;
    int warp = (blockIdx.x * blockDim.x + threadIdx.x) >> 5;
    int lane = threadIdx.x & 31;
    int nwarps = (gridDim.x * blockDim.x) >> 5;
    for (int i = warp; i < n; i += nwarps) {
        int4 r = g_ovf[i];
        float w = __int_as_float(r.w);
        float4 hv = h4[(size_t)r.x * 32 + lane];
        float4 c = {hv.x * w, hv.y * w, hv.z * w, hv.w * w};
        float* o = g_agg + ((size_t)r.y * 3 + r.z) * D + lane * 4;
        red_add_v4(o, c);
    }
}

// ---------------------------------------------------------------------------
// Fused GEMM (X[50000x512] @ Weff^T[512x128]) + bias + LayerNorm + ReLU.
// BM=64, BN=128, BK=32, 256 threads. Per-thread: 4 row-pairs x 4 cols,
// accumulated with packed fma.rn.f32x2 (2 fp32 FMA per instruction).
// LN fully in registers via warp shfl (no smem z round-trip).
// ---------------------------------------------------------------------------
__global__ __launch_bounds__(256) void gemm_ln_kernel(
    const float* __restrict__ h,
    const float* __restrict__ b,
    const float* __restrict__ gamma,
    const float* __restrict__ beta,
    float* __restrict__ out) {

    __shared__ float Xs[32][66];    // [k][node], stride 66 -> 8B-aligned pairs
    __shared__ float Ws[32][132];   // [k][col],  row stride 528B (16B aligned)

    const int tid = threadIdx.x;
    const int tx = tid & 31;        // lane: cols 4tx..4tx+3
    const int ty = tid >> 5;        // warp: rows ty*8..ty*8+7
    const int nodeBase = blockIdx.x * 64;

    u64 acc2[4][4];                 // [row-pair][col] packed {row2p, row2p+1}
#pragma unroll
    for (int p = 0; p < 4; p++)
#pragma unroll
        for (int j = 0; j < 4; j++) acc2[p][j] = 0ull;

    for (int k0 = 0; k0 < KDIM; k0 += 32) {
        // X tile -> Xs[k][node] (transposed; coalesced gmem reads)
#pragma unroll
        for (int it = 0; it < 8; it++) {
            int i = it * 256 + tid;
            int node = i >> 5;
            int kk = i & 31;
            int gn = nodeBase + node;
            int c = k0 + kk;
            float v = 0.f;
            if (gn < N_NODES) {
                v = (c < 128) ? h[(size_t)gn * 128 + c]
                              : g_agg[(size_t)gn * 384 + (c - 128)];
            }
            Xs[kk][node] = v;
        }
        // W tile: g_Weff is [k][col] -> float4 coalesced, conflict-free STS.128
#pragma unroll
        for (int it = 0; it < 4; it++) {
            int i = it * 256 + tid;       // 0..1023 float4s
            int kk = i >> 5;
            int c4 = (i & 31) * 4;
            *(float4*)&Ws[kk][c4] = *(const float4*)&g_Weff[(k0 + kk) * D + c4];
        }
        __syncthreads();

#pragma unroll
        for (int kk = 0; kk < 32; kk++) {
            float4 w4 = *(const float4*)&Ws[kk][tx * 4];
            u64 wd0 = dup_f32(w4.x);
            u64 wd1 = dup_f32(w4.y);
            u64 wd2 = dup_f32(w4.z);
            u64 wd3 = dup_f32(w4.w);
#pragma unroll
            for (int p = 0; p < 4; p++) {
                u64 a2 = *(const u64*)&Xs[kk][ty * 8 + 2 * p];  // {row, row+1}
                acc2[p][0] = fma_f32x2(a2, wd0, acc2[p][0]);
                acc2[p][1] = fma_f32x2(a2, wd1, acc2[p][1]);
                acc2[p][2] = fma_f32x2(a2, wd2, acc2[p][2]);
                acc2[p][3] = fma_f32x2(a2, wd3, acc2[p][3]);
            }
        }
        __syncthreads();
    }

    // Unpack accumulators: v[i][j] = z for row ty*8+i, col 4tx+j
    float v[8][4];
#pragma unroll
    for (int p = 0; p < 4; p++)
#pragma unroll
        for (int j = 0; j < 4; j++) {
            v[2 * p][j]     = __uint_as_float((unsigned)acc2[p][j]);
            v[2 * p + 1][j] = __uint_as_float((unsigned)(acc2[p][j] >> 32));
        }

    // Bias + LayerNorm + ReLU fully in registers (row lives in one warp).
    float4 bb = ((const float4*)b)[tx];
    float4 g4 = ((const float4*)gamma)[tx];
    float4 be = ((const float4*)beta)[tx];
#pragma unroll
    for (int i = 0; i < 8; i++) {
        int gn = nodeBase + ty * 8 + i;
        if (gn >= N_NODES) continue;   // uniform across warp
        float4 z;
        z.x = v[i][0] + bb.x;
        z.y = v[i][1] + bb.y;
        z.z = v[i][2] + bb.z;
        z.w = v[i][3] + bb.w;
        float s1 = z.x + z.y + z.z + z.w;
        float s2 = z.x * z.x + z.y * z.y + z.z * z.z + z.w * z.w;
#pragma unroll
        for (int off = 16; off > 0; off >>= 1) {
            s1 += __shfl_xor_sync(0xFFFFFFFF, s1, off);
            s2 += __shfl_xor_sync(0xFFFFFFFF, s2, off);
        }
        float mu = s1 * (1.0f / 128.0f);
        float var = s2 * (1.0f / 128.0f) - mu * mu;
        float rs = rsqrtf(var + 1e-5f);
        float4 o;
        o.x = fmaxf((z.x - mu) * rs * g4.x + be.x, 0.f);
        o.y = fmaxf((z.y - mu) * rs * g4.y + be.y, 0.f);
        o.z = fmaxf((z.z - mu) * rs * g4.z + be.z, 0.f);
        o.w = fmaxf((z.w - mu) * rs * g4.w + be.w, 0.f);
        ((float4*)(out + (size_t)gn * 128))[tx] = o;
    }
}

extern "C" void kernel_launch(void* const* d_in, const int* in_sizes, int n_in,
                              void* d_out, int out_size) {
    const float* h     = (const float*)d_in[0];
    const float* dist  = (const float*)d_in[1];
    const float* W     = (const float*)d_in[2];
    const float* b     = (const float*)d_in[3];
    const float* gamma = (const float*)d_in[4];
    const float* beta  = (const float*)d_in[5];
    const int* src     = (const int*)d_in[6];
    const int* dst     = (const int*)d_in[7];
    const int* pos     = (const int*)d_in[8];
    float* out = (float*)d_out;

    void* cntp = nullptr; cudaGetSymbolAddress(&cntp, g_count);
    void* novp = nullptr; cudaGetSymbolAddress(&novp, g_novf);
    cudaMemsetAsync(cntp, 0, N_NODES * sizeof(int));
    cudaMemsetAsync(novp, 0, sizeof(int));

    weff_kernel<<<(D * KDIM + 255) / 256, 256>>>(W);

    fill_kernel<<<(E_EDGES + 255) / 256, 256>>>(dist, src, dst, pos);

    agg_kernel<<<(N_NODES * 32 + 255) / 256, 256>>>((const float4*)h);

    fixup_kernel<<<8, 256>>>((const float4*)h);

    gemm_ln_kernel<<<(N_NODES + 63) / 64, 256>>>(h, b, gamma, beta, out);
}

// round 6
// speedup vs baseline: 2.7214x; 1.9584x over previous
#include <cuda_runtime.h>
#include <cuda_bf16.h>

#define N_NODES 50000
#define E_EDGES 800000
#define D 128
#define KDIM 512      // effective concat width after folding t into r
#define CAP 96
#define OVF_CAP 4096

typedef unsigned long long u64;
typedef unsigned int u32;

// Scratch (allocation-free rule: __device__ globals)
__device__ float g_agg[(size_t)N_NODES * 3 * D];          // 76.8 MB
__device__ __nv_bfloat16 g_Wh[D * KDIM];                  // [n][k] 128x512 bf16
__device__ __nv_bfloat16 g_Wl[D * KDIM];
__device__ u64 g_rec[(size_t)N_NODES * CAP];              // 38.4 MB
__device__ int g_cnt[N_NODES + 1];                        // [N_NODES] = overflow count
__device__ int4 g_ovf[OVF_CAP];

// ---------------------------------------------------------------------------
// Fold W[:,512:640] into W[:,128:256]; split into bf16 hi/lo, [n][k] layout.
// ---------------------------------------------------------------------------
__global__ void weff_kernel(const float* __restrict__ W) {
    int i = blockIdx.x * blockDim.x + threadIdx.x;
    if (i >= D * KDIM) return;
    int n = i >> 9;          // out feature 0..127
    int c = i & 511;         // concat col  0..511
    float v = W[n * 640 + c];
    if (c >= 128 && c < 256) v += W[n * 640 + c + 384];
    __nv_bfloat16 hi = __float2bfloat16(v);
    __nv_bfloat16 lo = __float2bfloat16(v - __bfloat162float(hi));
    g_Wh[n * KDIM + c] = hi;
    g_Wl[n * KDIM + c] = lo;
}

// ---------------------------------------------------------------------------
// Bucket contributing edges by dst. Record = (src | p<<16, f32 w) packed u64.
// ---------------------------------------------------------------------------
__global__ void fill_kernel(const float* __restrict__ dist,
                            const int* __restrict__ src,
                            const int* __restrict__ dst,
                            const int* __restrict__ pos) {
    int e = blockIdx.x * blockDim.x + threadIdx.x;
    if (e >= E_EDGES) return;
    int p = pos[e];
    if (p >= 3) return;
    int d = dst[e];
    int s = src[e];
    float w = dist[e];
    int slot = atomicAdd(&g_cnt[d], 1);
    if (slot < CAP) {
        unsigned lo = (unsigned)s | ((unsigned)p << 16);
        unsigned hi = __float_as_uint(w);
        g_rec[(size_t)d * CAP + slot] = (u64)lo | ((u64)hi << 32);
    } else {
        int o = atomicAdd(&g_cnt[N_NODES], 1);
        if (o < OVF_CAP) g_ovf[o] = make_int4(s, d, p, __float_as_int(w));
    }
}

// ---------------------------------------------------------------------------
// Aggregation: one warp per dst node, 3 direction channels in registers.
// ---------------------------------------------------------------------------
__global__ __launch_bounds__(256) void agg_kernel(const float4* __restrict__ h4) {
    int idx = blockIdx.x * blockDim.x + threadIdx.x;
    int d = idx >> 5;
    int lane = idx & 31;
    if (d >= N_NODES) return;
    int deg = g_cnt[d];
    if (deg > CAP) deg = CAP;
    float4 a0 = {0.f, 0.f, 0.f, 0.f};
    float4 a1 = {0.f, 0.f, 0.f, 0.f};
    float4 a2 = {0.f, 0.f, 0.f, 0.f};
    const u64* rp = g_rec + (size_t)d * CAP;
#pragma unroll 4
    for (int i = 0; i < deg; i++) {
        u64 rec = __ldg(rp + i);
        unsigned lo = (unsigned)rec;
        float w = __uint_as_float((unsigned)(rec >> 32));
        int s = lo & 0xFFFF;
        int p = lo >> 16;
        float4 hv = h4[(size_t)s * 32 + lane];
        float4 c = {hv.x * w, hv.y * w, hv.z * w, hv.w * w};
        if (p == 0)      { a0.x += c.x; a0.y += c.y; a0.z += c.z; a0.w += c.w; }
        else if (p == 1) { a1.x += c.x; a1.y += c.y; a1.z += c.z; a1.w += c.w; }
        else             { a2.x += c.x; a2.y += c.y; a2.z += c.z; a2.w += c.w; }
    }
    float4* o = (float4*)(g_agg + (size_t)d * 384);
    o[lane] = a0;
    o[32 + lane] = a1;
    o[64 + lane] = a2;
}

// ---------------------------------------------------------------------------
// Overflow fixup (normally zero work).
// ---------------------------------------------------------------------------
__device__ __forceinline__ void red_add_v4(float* p, float4 v) {
    asm volatile("red.global.add.v4.f32 [%0], {%1, %2, %3, %4};"
                 :: "l"(p), "f"(v.x), "f"(v.y), "f"(v.z), "f"(v.w) : "memory");
}
__global__ void fixup_kernel(const float4* __restrict__ h4) {
    int n = g_cnt[N_NODES];
    if (n > OVF_CAP) n = OVF_CAP;
    int warp = (blockIdx.x * blockDim.x + threadIdx.x) >> 5;
    int lane = threadIdx.x & 31;
    int nwarps = (gridDim.x * blockDim.x) >> 5;
    for (int i = warp; i < n; i += nwarps) {
        int4 r = g_ovf[i];
        float w = __int_as_float(r.w);
        float4 hv = h4[(size_t)r.x * 32 + lane];
        float4 c = {hv.x * w, hv.y * w, hv.z * w, hv.w * w};
        red_add_v4(g_agg + ((size_t)r.y * 3 + r.z) * D + lane * 4, c);
    }
}

// ---------------------------------------------------------------------------
// Split-bf16 mma.sync GEMM (X[50048x512] @ Weff^T) + bias + LayerNorm + ReLU.
// z = Xh*Wh + Xl*Wh + Xh*Wl (fp32 accum). CTA: 128 rows x 128 cols.
// 8 warps: 4(M) x 2(N); warp tile 32x64 = 2x8 m16n8k16 tiles.
// Smem tiles padded to 72 halves/row -> conflict-free fragment LDS.
// ---------------------------------------------------------------------------
#define SM_BIAS 0
#define SM_GAMMA 512
#define SM_BETA 1024
#define SM_ROWS 1536                 // float2 rowsums [2][128] = 2048 B
#define SM_AH 3584
#define SM_AL (SM_AH + 18432)
#define SM_BH (SM_AH + 2 * 18432)
#define SM_BL (SM_AH + 3 * 18432)
#define SMEM_GEMM (SM_AH + 4 * 18432)   // 77312 B

__device__ __forceinline__ void mma_bf16(float* c, u32 a0, u32 a1, u32 a2, u32 a3,
                                         u32 b0, u32 b1) {
    asm volatile(
        "mma.sync.aligned.m16n8k16.row.col.f32.bf16.bf16.f32 "
        "{%0,%1,%2,%3}, {%4,%5,%6,%7}, {%8,%9}, {%0,%1,%2,%3};"
        : "+f"(c[0]), "+f"(c[1]), "+f"(c[2]), "+f"(c[3])
        : "r"(a0), "r"(a1), "r"(a2), "r"(a3), "r"(b0), "r"(b1));
}

__global__ __launch_bounds__(256) void gemm_ln_kernel(
    const float* __restrict__ h,
    const float* __restrict__ bias,
    const float* __restrict__ gamma,
    const float* __restrict__ beta,
    float* __restrict__ out) {

    extern __shared__ char smem[];
    const int tid = threadIdx.x;
    const int lane = tid & 31;
    const int wid = tid >> 5;
    const int warpM = wid >> 1;          // 0..3
    const int warpN = wid & 1;           // 0..1
    const int nodeBase = blockIdx.x * 128;
    const int laneRow = lane >> 2;       // 0..7
    const int laneK2 = (lane & 3) * 2;   // 0,2,4,6

    if (tid < 128) {
        *(float*)(smem + SM_BIAS + tid * 4) = bias[tid];
        *(float*)(smem + SM_GAMMA + tid * 4) = gamma[tid];
        *(float*)(smem + SM_BETA + tid * 4) = beta[tid];
    }

    float acc[2][8][4];
#pragma unroll
    for (int mt = 0; mt < 2; mt++)
#pragma unroll
        for (int nt = 0; nt < 8; nt++)
#pragma unroll
            for (int q = 0; q < 4; q++) acc[mt][nt][q] = 0.f;

    for (int c = 0; c < 8; c++) {
        // ---- X tile: f32 load, split bf16 hi/lo, store [row][k] stride 72 ----
        const float* xsrc = (c < 2) ? h : g_agg;
        const int rstride = (c < 2) ? 128 : 384;
        const int coff = (c < 2) ? c * 64 : c * 64 - 128;
#pragma unroll
        for (int it = 0; it < 8; it++) {
            int u = tid + it * 256;       // 0..2047 float4 units
            int row = u >> 4;
            int c4 = u & 15;
            int gn = nodeBase + row;
            float4 f = make_float4(0.f, 0.f, 0.f, 0.f);
            if (gn < N_NODES)
                f = *(const float4*)(xsrc + (size_t)gn * rstride + coff + c4 * 4);
            float ff[4] = {f.x, f.y, f.z, f.w};
            u32 hw[2], lw[2];
#pragma unroll
            for (int j = 0; j < 2; j++) {
                __nv_bfloat16 h0 = __float2bfloat16(ff[2 * j]);
                __nv_bfloat16 h1 = __float2bfloat16(ff[2 * j + 1]);
                __nv_bfloat16 l0 = __float2bfloat16(ff[2 * j] - __bfloat162float(h0));
                __nv_bfloat16 l1 = __float2bfloat16(ff[2 * j + 1] - __bfloat162float(h1));
                hw[j] = (u32)__bfloat16_as_ushort(h0) | ((u32)__bfloat16_as_ushort(h1) << 16);
                lw[j] = (u32)__bfloat16_as_ushort(l0) | ((u32)__bfloat16_as_ushort(l1) << 16);
            }
            int off = row * 144 + c4 * 8;    // bytes (stride 72 halves)
            *(uint2*)(smem + SM_AH + off) = make_uint2(hw[0], hw[1]);
            *(uint2*)(smem + SM_AL + off) = make_uint2(lw[0], lw[1]);
        }
        // ---- B tiles: bf16 copy [n][k] stride 72 ----
#pragma unroll
        for (int it = 0; it < 4; it++) {
            int u = tid + it * 256;       // 0..1023 8-half units
            int n = u >> 3;
            int c8 = u & 7;
            int goff = (n * KDIM + c * 64 + c8 * 8) * 2;
            int soff = n * 144 + c8 * 16;
            *(uint4*)(smem + SM_BH + soff) = *(const uint4*)((const char*)g_Wh + goff);
            *(uint4*)(smem + SM_BL + soff) = *(const uint4*)((const char*)g_Wl + goff);
        }
        __syncthreads();

#pragma unroll
        for (int ks = 0; ks < 4; ks++) {
            const int kb = ks * 32 + laneK2 * 2;   // byte offset of k within row
            u32 ah[2][4], bb[8][2];
            // A hi fragments
#pragma unroll
            for (int mt = 0; mt < 2; mt++) {
                int base = SM_AH + (warpM * 32 + mt * 16 + laneRow) * 144 + kb;
                ah[mt][0] = *(const u32*)(smem + base);
                ah[mt][1] = *(const u32*)(smem + base + 8 * 144);
                ah[mt][2] = *(const u32*)(smem + base + 16);
                ah[mt][3] = *(const u32*)(smem + base + 8 * 144 + 16);
            }
            // B hi fragments
#pragma unroll
            for (int nt = 0; nt < 8; nt++) {
                int base = SM_BH + (warpN * 64 + nt * 8 + laneRow) * 144 + kb;
                bb[nt][0] = *(const u32*)(smem + base);
                bb[nt][1] = *(const u32*)(smem + base + 16);
            }
#pragma unroll
            for (int mt = 0; mt < 2; mt++)
#pragma unroll
                for (int nt = 0; nt < 8; nt++)
                    mma_bf16(acc[mt][nt], ah[mt][0], ah[mt][1], ah[mt][2], ah[mt][3],
                             bb[nt][0], bb[nt][1]);
            // A lo x B hi
            {
                u32 al[4];
#pragma unroll
                for (int mt = 0; mt < 2; mt++) {
                    int base = SM_AL + (warpM * 32 + mt * 16 + laneRow) * 144 + kb;
                    al[0] = *(const u32*)(smem + base);
                    al[1] = *(const u32*)(smem + base + 8 * 144);
                    al[2] = *(const u32*)(smem + base + 16);
                    al[3] = *(const u32*)(smem + base + 8 * 144 + 16);
#pragma unroll
                    for (int nt = 0; nt < 8; nt++)
                        mma_bf16(acc[mt][nt], al[0], al[1], al[2], al[3],
                                 bb[nt][0], bb[nt][1]);
                }
            }
            // A hi x B lo
#pragma unroll
            for (int nt = 0; nt < 8; nt++) {
                int base = SM_BL + (warpN * 64 + nt * 8 + laneRow) * 144 + kb;
                bb[nt][0] = *(const u32*)(smem + base);
                bb[nt][1] = *(const u32*)(smem + base + 16);
            }
#pragma unroll
            for (int mt = 0; mt < 2; mt++)
#pragma unroll
                for (int nt = 0; nt < 8; nt++)
                    mma_bf16(acc[mt][nt], ah[mt][0], ah[mt][1], ah[mt][2], ah[mt][3],
                             bb[nt][0], bb[nt][1]);
        }
        __syncthreads();
    }

    // ---- Epilogue: bias + LN sums from fragments ----
    const float* sbias = (const float*)(smem + SM_BIAS);
    float s1[2][2], s2[2][2];
#pragma unroll
    for (int mt = 0; mt < 2; mt++) { s1[mt][0] = s1[mt][1] = s2[mt][0] = s2[mt][1] = 0.f; }
#pragma unroll
    for (int mt = 0; mt < 2; mt++)
#pragma unroll
        for (int nt = 0; nt < 8; nt++) {
            int j0 = warpN * 64 + nt * 8 + laneK2;
            float b0 = sbias[j0], b1 = sbias[j0 + 1];
            acc[mt][nt][0] += b0; acc[mt][nt][1] += b1;
            acc[mt][nt][2] += b0; acc[mt][nt][3] += b1;
            s1[mt][0] += acc[mt][nt][0] + acc[mt][nt][1];
            s2[mt][0] += acc[mt][nt][0] * acc[mt][nt][0] + acc[mt][nt][1] * acc[mt][nt][1];
            s1[mt][1] += acc[mt][nt][2] + acc[mt][nt][3];
            s2[mt][1] += acc[mt][nt][2] * acc[mt][nt][2] + acc[mt][nt][3] * acc[mt][nt][3];
        }
    // reduce over the 4 lanes of each row quad
#pragma unroll
    for (int mt = 0; mt < 2; mt++)
#pragma unroll
        for (int rh = 0; rh < 2; rh++) {
            s1[mt][rh] += __shfl_xor_sync(0xFFFFFFFF, s1[mt][rh], 1);
            s1[mt][rh] += __shfl_xor_sync(0xFFFFFFFF, s1[mt][rh], 2);
            s2[mt][rh] += __shfl_xor_sync(0xFFFFFFFF, s2[mt][rh], 1);
            s2[mt][rh] += __shfl_xor_sync(0xFFFFFFFF, s2[mt][rh], 2);
        }
    if ((lane & 3) == 0) {
#pragma unroll
        for (int mt = 0; mt < 2; mt++)
#pragma unroll
            for (int rh = 0; rh < 2; rh++) {
                int row = warpM * 32 + mt * 16 + rh * 8 + laneRow;
                *(float2*)(smem + SM_ROWS + (warpN * 128 + row) * 8) =
                    make_float2(s1[mt][rh], s2[mt][rh]);
            }
    }
    __syncthreads();

    const float* sg = (const float*)(smem + SM_GAMMA);
    const float* sbeta = (const float*)(smem + SM_BETA);
#pragma unroll
    for (int mt = 0; mt < 2; mt++)
#pragma unroll
        for (int rh = 0; rh < 2; rh++) {
            int row = warpM * 32 + mt * 16 + rh * 8 + laneRow;
            float2 p0 = *(const float2*)(smem + SM_ROWS + row * 8);
            float2 p1 = *(const float2*)(smem + SM_ROWS + (128 + row) * 8);
            float mu = (p0.x + p1.x) * (1.0f / 128.0f);
            float var = (p0.y + p1.y) * (1.0f / 128.0f) - mu * mu;
            float rs = rsqrtf(var + 1e-5f);
            int gn = nodeBase + row;
            if (gn < N_NODES) {
#pragma unroll
                for (int nt = 0; nt < 8; nt++) {
                    int j0 = warpN * 64 + nt * 8 + laneK2;
                    float z0 = acc[mt][nt][rh * 2 + 0];
                    float z1 = acc[mt][nt][rh * 2 + 1];
                    float2 o;
                    o.x = fmaxf((z0 - mu) * rs * sg[j0] + sbeta[j0], 0.f);
                    o.y = fmaxf((z1 - mu) * rs * sg[j0 + 1] + sbeta[j0 + 1], 0.f);
                    *(float2*)(out + (size_t)gn * 128 + j0) = o;
                }
            }
        }
}

extern "C" void kernel_launch(void* const* d_in, const int* in_sizes, int n_in,
                              void* d_out, int out_size) {
    const float* h     = (const float*)d_in[0];
    const float* dist  = (const float*)d_in[1];
    const float* W     = (const float*)d_in[2];
    const float* b     = (const float*)d_in[3];
    const float* gamma = (const float*)d_in[4];
    const float* beta  = (const float*)d_in[5];
    const int* src     = (const int*)d_in[6];
    const int* dst     = (const int*)d_in[7];
    const int* pos     = (const int*)d_in[8];
    float* out = (float*)d_out;

    cudaFuncSetAttribute(gemm_ln_kernel,
                         cudaFuncAttributeMaxDynamicSharedMemorySize, SMEM_GEMM);

    void* cntp = nullptr; cudaGetSymbolAddress(&cntp, g_cnt);
    cudaMemsetAsync(cntp, 0, (N_NODES + 1) * sizeof(int));

    weff_kernel<<<(D * KDIM + 255) / 256, 256>>>(W);

    fill_kernel<<<(E_EDGES + 255) / 256, 256>>>(dist, src, dst, pos);

    agg_kernel<<<(N_NODES * 32 + 255) / 256, 256>>>((const float4*)h);

    fixup_kernel<<<8, 256>>>((const float4*)h);

    gemm_ln_kernel<<<(N_NODES + 127) / 128, 256, SMEM_GEMM>>>(h, b, gamma, beta, out);
}

// round 7
// speedup vs baseline: 3.4224x; 1.2576x over previous
#include <cuda_runtime.h>
#include <cuda_bf16.h>

#define N_NODES 50000
#define E_EDGES 800000
#define D 128
#define KDIM 512      // effective concat width after folding t into r
#define CAP 96
#define OVF_CAP 4096

typedef unsigned long long u64;
typedef unsigned int u32;

// Scratch (allocation-free rule: __device__ globals)
__device__ float g_agg[(size_t)N_NODES * 3 * D];          // 76.8 MB
__device__ __nv_bfloat16 g_Wh[D * KDIM];                  // [n][k] 128x512 bf16
__device__ __nv_bfloat16 g_Wl[D * KDIM];
__device__ u64 g_rec[(size_t)N_NODES * CAP];              // 38.4 MB
__device__ int g_cnt[N_NODES + 1];                        // [N_NODES] = overflow count
__device__ int4 g_ovf[OVF_CAP];

// ---------------------------------------------------------------------------
// Fold W[:,512:640] into W[:,128:256]; split into bf16 hi/lo, [n][k] layout.
// ---------------------------------------------------------------------------
__global__ void weff_kernel(const float* __restrict__ W) {
    int i = blockIdx.x * blockDim.x + threadIdx.x;
    if (i >= D * KDIM) return;
    int n = i >> 9;          // out feature 0..127
    int c = i & 511;         // concat col  0..511
    float v = W[n * 640 + c];
    if (c >= 128 && c < 256) v += W[n * 640 + c + 384];
    __nv_bfloat16 hi = __float2bfloat16(v);
    __nv_bfloat16 lo = __float2bfloat16(v - __bfloat162float(hi));
    g_Wh[n * KDIM + c] = hi;
    g_Wl[n * KDIM + c] = lo;
}

// ---------------------------------------------------------------------------
// Bucket contributing edges by dst. Record = (src | p<<16, f32 w) packed u64.
// ---------------------------------------------------------------------------
__global__ void fill_kernel(const float* __restrict__ dist,
                            const int* __restrict__ src,
                            const int* __restrict__ dst,
                            const int* __restrict__ pos) {
    int e = blockIdx.x * blockDim.x + threadIdx.x;
    if (e >= E_EDGES) return;
    int p = pos[e];
    if (p >= 3) return;
    int d = dst[e];
    int s = src[e];
    float w = dist[e];
    int slot = atomicAdd(&g_cnt[d], 1);
    if (slot < CAP) {
        unsigned lo = (unsigned)s | ((unsigned)p << 16);
        unsigned hi = __float_as_uint(w);
        g_rec[(size_t)d * CAP + slot] = (u64)lo | ((u64)hi << 32);
    } else {
        int o = atomicAdd(&g_cnt[N_NODES], 1);
        if (o < OVF_CAP) g_ovf[o] = make_int4(s, d, p, __float_as_int(w));
    }
}

// ---------------------------------------------------------------------------
// Aggregation: one warp per dst node, 3 direction channels in registers.
// ---------------------------------------------------------------------------
__global__ __launch_bounds__(256) void agg_kernel(const float4* __restrict__ h4) {
    int idx = blockIdx.x * blockDim.x + threadIdx.x;
    int d = idx >> 5;
    int lane = idx & 31;
    if (d >= N_NODES) return;
    int deg = g_cnt[d];
    if (deg > CAP) deg = CAP;
    float4 a0 = {0.f, 0.f, 0.f, 0.f};
    float4 a1 = {0.f, 0.f, 0.f, 0.f};
    float4 a2 = {0.f, 0.f, 0.f, 0.f};
    const u64* rp = g_rec + (size_t)d * CAP;
#pragma unroll 4
    for (int i = 0; i < deg; i++) {
        u64 rec = __ldg(rp + i);
        unsigned lo = (unsigned)rec;
        float w = __uint_as_float((unsigned)(rec >> 32));
        int s = lo & 0xFFFF;
        int p = lo >> 16;
        float4 hv = h4[(size_t)s * 32 + lane];
        float4 c = {hv.x * w, hv.y * w, hv.z * w, hv.w * w};
        if (p == 0)      { a0.x += c.x; a0.y += c.y; a0.z += c.z; a0.w += c.w; }
        else if (p == 1) { a1.x += c.x; a1.y += c.y; a1.z += c.z; a1.w += c.w; }
        else             { a2.x += c.x; a2.y += c.y; a2.z += c.z; a2.w += c.w; }
    }
    float4* o = (float4*)(g_agg + (size_t)d * 384);
    o[lane] = a0;
    o[32 + lane] = a1;
    o[64 + lane] = a2;
}

// ---------------------------------------------------------------------------
// Overflow fixup (normally zero work).
// ---------------------------------------------------------------------------
__device__ __forceinline__ void red_add_v4(float* p, float4 v) {
    asm volatile("red.global.add.v4.f32 [%0], {%1, %2, %3, %4};"
                 :: "l"(p), "f"(v.x), "f"(v.y), "f"(v.z), "f"(v.w) : "memory");
}
__global__ void fixup_kernel(const float4* __restrict__ h4) {
    int n = g_cnt[N_NODES];
    if (n > OVF_CAP) n = OVF_CAP;
    int warp = (blockIdx.x * blockDim.x + threadIdx.x) >> 5;
    int lane = threadIdx.x & 31;
    int nwarps = (gridDim.x * blockDim.x) >> 5;
    for (int i = warp; i < n; i += nwarps) {
        int4 r = g_ovf[i];
        float w = __int_as_float(r.w);
        float4 hv = h4[(size_t)r.x * 32 + lane];
        float4 c = {hv.x * w, hv.y * w, hv.z * w, hv.w * w};
        red_add_v4(g_agg + ((size_t)r.y * 3 + r.z) * D + lane * 4, c);
    }
}

// ---------------------------------------------------------------------------
// Split-bf16 mma.sync GEMM + bias + LayerNorm + ReLU.
// z = Xh*Wh + Xl*Wh + Xh*Wl. CTA: 128x128, 8 warps 4(M)x2(N).
// Tiles: XOR-swizzled 128B rows; ldmatrix.x4 fragments; cp.async
// double-buffered B tiles. 2 CTAs/SM.
// ---------------------------------------------------------------------------
#define SM_BIAS 0
#define SM_GAMMA 512
#define SM_BETA 1024
#define SM_ROWS 1536                 // float2 rowsums [2][128] = 2048 B
#define SM_XH 3584
#define SM_XL (SM_XH + 16384)
#define SM_B0 (SM_XL + 16384)        // 2 buffers x (Bh 16K + Bl 16K)
#define SMEM_GEMM (SM_B0 + 2 * 32768)   // 101888 B

__device__ __forceinline__ void mma_bf16(float* c, u32 a0, u32 a1, u32 a2, u32 a3,
                                         u32 b0, u32 b1) {
    asm volatile(
        "mma.sync.aligned.m16n8k16.row.col.f32.bf16.bf16.f32 "
        "{%0,%1,%2,%3}, {%4,%5,%6,%7}, {%8,%9}, {%0,%1,%2,%3};"
        : "+f"(c[0]), "+f"(c[1]), "+f"(c[2]), "+f"(c[3])
        : "r"(a0), "r"(a1), "r"(a2), "r"(a3), "r"(b0), "r"(b1));
}
#define LDSM4(r0, r1, r2, r3, addr) \
    asm volatile("ldmatrix.sync.aligned.m8n8.x4.shared.b16 {%0,%1,%2,%3}, [%4];" \
                 : "=r"(r0), "=r"(r1), "=r"(r2), "=r"(r3) : "r"(addr))
#define CP16(dst, src) \
    asm volatile("cp.async.cg.shared.global [%0], [%1], 16;" :: "r"(dst), "l"(src))
#define CP_COMMIT() asm volatile("cp.async.commit_group;" ::: "memory")
#define CP_WAIT1() asm volatile("cp.async.wait_group 1;" ::: "memory")
#define CP_WAIT0() asm volatile("cp.async.wait_group 0;" ::: "memory")

__device__ __forceinline__ u32 smem_u32(const void* p) {
    u32 a;
    asm("{ .reg .u64 t; cvta.to.shared.u64 t, %1; cvt.u32.u64 %0, t; }"
        : "=r"(a) : "l"(p));
    return a;
}

__global__ __launch_bounds__(256, 2) void gemm_ln_kernel(
    const float* __restrict__ h,
    const float* __restrict__ bias,
    const float* __restrict__ gamma,
    const float* __restrict__ beta,
    float* __restrict__ out) {

    extern __shared__ char smem[];
    const u32 sbase = smem_u32(smem);
    const int tid = threadIdx.x;
    const int lane = tid & 31;
    const int wid = tid >> 5;
    const int warpM = wid >> 1;          // 0..3
    const int warpN = wid & 1;           // 0..1
    const int nodeBase = blockIdx.x * 128;
    const int laneRow = lane >> 2;       // 0..7
    const int laneK2 = (lane & 3) * 2;   // 0,2,4,6
    const int lr = lane & 7;             // ldmatrix row within group
    const int lg = lane >> 3;            // ldmatrix lane group 0..3

    // ldmatrix address components
    const int aRowB = warpM * 32 + (lg & 1) * 8 + lr;   // + mt*16
    const int aUG = lg >> 1;
    const int aSw = aRowB & 7;
    const int bRowB = warpN * 64 + (lg >> 1) * 8 + lr;  // + ntp*16
    const int bUG = lg & 1;
    const int bSw = bRowB & 7;

    if (tid < 128) {
        *(float*)(smem + SM_BIAS + tid * 4) = bias[tid];
        *(float*)(smem + SM_GAMMA + tid * 4) = gamma[tid];
        *(float*)(smem + SM_BETA + tid * 4) = beta[tid];
    }

    float acc[2][8][4];
#pragma unroll
    for (int mt = 0; mt < 2; mt++)
#pragma unroll
        for (int nt = 0; nt < 8; nt++)
#pragma unroll
            for (int q = 0; q < 4; q++) acc[mt][nt][q] = 0.f;

    // Prologue: cp.async B(0) into buffer 0
    {
        const int n = tid >> 3, c8 = tid & 7;            // covers via 4 iters below
#pragma unroll
        for (int it = 0; it < 4; it++) {
            int u = tid + it * 256;
            int nn = u >> 3, cc = u & 7;
            u32 dsto = (u32)(nn * 128 + (((cc ^ (nn & 7))) << 4));
            CP16(sbase + SM_B0 + dsto, (const char*)g_Wh + (size_t)(nn * KDIM + cc * 8) * 2);
            CP16(sbase + SM_B0 + 16384 + dsto, (const char*)g_Wl + (size_t)(nn * KDIM + cc * 8) * 2);
        }
        (void)n; (void)c8;
        CP_COMMIT();
    }

    for (int c = 0; c < 8; c++) {
        // ---- X tile fill: f32 load, split bf16 hi/lo, swizzled STS ----
        const float* xsrc = (c < 2) ? h : g_agg;
        const int rstride = (c < 2) ? 128 : 384;
        const int coff = (c < 2) ? c * 64 : c * 64 - 128;
#pragma unroll
        for (int it = 0; it < 8; it++) {
            int u = tid + it * 256;       // 0..2047 float4 units
            int row = u >> 4;
            int c4 = u & 15;
            int gn = nodeBase + row;
            float4 f = make_float4(0.f, 0.f, 0.f, 0.f);
            if (gn < N_NODES)
                f = *(const float4*)(xsrc + (size_t)gn * rstride + coff + c4 * 4);
            float ff[4] = {f.x, f.y, f.z, f.w};
            u32 hw[2], lw[2];
#pragma unroll
            for (int j = 0; j < 2; j++) {
                __nv_bfloat16 h0 = __float2bfloat16(ff[2 * j]);
                __nv_bfloat16 h1 = __float2bfloat16(ff[2 * j + 1]);
                __nv_bfloat16 l0 = __float2bfloat16(ff[2 * j] - __bfloat162float(h0));
                __nv_bfloat16 l1 = __float2bfloat16(ff[2 * j + 1] - __bfloat162float(h1));
                hw[j] = (u32)__bfloat16_as_ushort(h0) | ((u32)__bfloat16_as_ushort(h1) << 16);
                lw[j] = (u32)__bfloat16_as_ushort(l0) | ((u32)__bfloat16_as_ushort(l1) << 16);
            }
            int off = row * 128 + ((((c4 >> 1) ^ (row & 7))) << 4) + (c4 & 1) * 8;
            *(uint2*)(smem + SM_XH + off) = make_uint2(hw[0], hw[1]);
            *(uint2*)(smem + SM_XL + off) = make_uint2(lw[0], lw[1]);
        }
        // ---- cp.async B(c+1) into alternate buffer ----
        if (c < 7) {
            int nb = SM_B0 + ((c + 1) & 1) * 32768;
            int kbase = (c + 1) * 64;
#pragma unroll
            for (int it = 0; it < 4; it++) {
                int u = tid + it * 256;
                int nn = u >> 3, cc = u & 7;
                u32 dsto = (u32)(nn * 128 + (((cc ^ (nn & 7))) << 4));
                CP16(sbase + nb + dsto,
                     (const char*)g_Wh + (size_t)(nn * KDIM + kbase + cc * 8) * 2);
                CP16(sbase + nb + 16384 + dsto,
                     (const char*)g_Wl + (size_t)(nn * KDIM + kbase + cc * 8) * 2);
            }
            CP_COMMIT();
            CP_WAIT1();     // B(c) complete
        } else {
            CP_WAIT0();
        }
        __syncthreads();

        // ---- MMA mainloop ----
        const u32 xh = sbase + SM_XH;
        const u32 xl = sbase + SM_XL;
        const u32 bh = sbase + SM_B0 + (c & 1) * 32768;
        const u32 bl = bh + 16384;
#pragma unroll
        for (int ks = 0; ks < 4; ks++) {
            u32 ah[2][4], al[2][4], bf[8][2];
            const int aCol = ((2 * ks + aUG) ^ aSw) << 4;
            const int bCol = ((2 * ks + bUG) ^ bSw) << 4;
#pragma unroll
            for (int mt = 0; mt < 2; mt++) {
                u32 ro = (u32)((aRowB + mt * 16) * 128 + aCol);
                LDSM4(ah[mt][0], ah[mt][1], ah[mt][2], ah[mt][3], xh + ro);
            }
#pragma unroll
            for (int mt = 0; mt < 2; mt++) {
                u32 ro = (u32)((aRowB + mt * 16) * 128 + aCol);
                LDSM4(al[mt][0], al[mt][1], al[mt][2], al[mt][3], xl + ro);
            }
#pragma unroll
            for (int ntp = 0; ntp < 4; ntp++) {
                u32 ro = (u32)((bRowB + ntp * 16) * 128 + bCol);
                LDSM4(bf[2 * ntp][0], bf[2 * ntp][1],
                      bf[2 * ntp + 1][0], bf[2 * ntp + 1][1], bh + ro);
            }
#pragma unroll
            for (int mt = 0; mt < 2; mt++)
#pragma unroll
                for (int nt = 0; nt < 8; nt++)
                    mma_bf16(acc[mt][nt], ah[mt][0], ah[mt][1], ah[mt][2], ah[mt][3],
                             bf[nt][0], bf[nt][1]);
#pragma unroll
            for (int mt = 0; mt < 2; mt++)
#pragma unroll
                for (int nt = 0; nt < 8; nt++)
                    mma_bf16(acc[mt][nt], al[mt][0], al[mt][1], al[mt][2], al[mt][3],
                             bf[nt][0], bf[nt][1]);
            // reload B lo
#pragma unroll
            for (int ntp = 0; ntp < 4; ntp++) {
                u32 ro = (u32)((bRowB + ntp * 16) * 128 + bCol);
                LDSM4(bf[2 * ntp][0], bf[2 * ntp][1],
                      bf[2 * ntp + 1][0], bf[2 * ntp + 1][1], bl + ro);
            }
#pragma unroll
            for (int mt = 0; mt < 2; mt++)
#pragma unroll
                for (int nt = 0; nt < 8; nt++)
                    mma_bf16(acc[mt][nt], ah[mt][0], ah[mt][1], ah[mt][2], ah[mt][3],
                             bf[nt][0], bf[nt][1]);
        }
        __syncthreads();
    }

    // ---- Epilogue: bias + LN sums from fragments ----
    const float* sbias = (const float*)(smem + SM_BIAS);
    float s1[2][2], s2[2][2];
#pragma unroll
    for (int mt = 0; mt < 2; mt++) { s1[mt][0] = s1[mt][1] = s2[mt][0] = s2[mt][1] = 0.f; }
#pragma unroll
    for (int mt = 0; mt < 2; mt++)
#pragma unroll
        for (int nt = 0; nt < 8; nt++) {
            int j0 = warpN * 64 + nt * 8 + laneK2;
            float b0 = sbias[j0], b1 = sbias[j0 + 1];
            acc[mt][nt][0] += b0; acc[mt][nt][1] += b1;
            acc[mt][nt][2] += b0; acc[mt][nt][3] += b1;
            s1[mt][0] += acc[mt][nt][0] + acc[mt][nt][1];
            s2[mt][0] += acc[mt][nt][0] * acc[mt][nt][0] + acc[mt][nt][1] * acc[mt][nt][1];
            s1[mt][1] += acc[mt][nt][2] + acc[mt][nt][3];
            s2[mt][1] += acc[mt][nt][2] * acc[mt][nt][2] + acc[mt][nt][3] * acc[mt][nt][3];
        }
#pragma unroll
    for (int mt = 0; mt < 2; mt++)
#pragma unroll
        for (int rh = 0; rh < 2; rh++) {
            s1[mt][rh] += __shfl_xor_sync(0xFFFFFFFF, s1[mt][rh], 1);
            s1[mt][rh] += __shfl_xor_sync(0xFFFFFFFF, s1[mt][rh], 2);
            s2[mt][rh] += __shfl_xor_sync(0xFFFFFFFF, s2[mt][rh], 1);
            s2[mt][rh] += __shfl_xor_sync(0xFFFFFFFF, s2[mt][rh], 2);
        }
    if ((lane & 3) == 0) {
#pragma unroll
        for (int mt = 0; mt < 2; mt++)
#pragma unroll
            for (int rh = 0; rh < 2; rh++) {
                int row = warpM * 32 + mt * 16 + rh * 8 + laneRow;
                *(float2*)(smem + SM_ROWS + (warpN * 128 + row) * 8) =
                    make_float2(s1[mt][rh], s2[mt][rh]);
            }
    }
    __syncthreads();

    const float* sg = (const float*)(smem + SM_GAMMA);
    const float* sbeta = (const float*)(smem + SM_BETA);
#pragma unroll
    for (int mt = 0; mt < 2; mt++)
#pragma unroll
        for (int rh = 0; rh < 2; rh++) {
            int row = warpM * 32 + mt * 16 + rh * 8 + laneRow;
            float2 p0 = *(const float2*)(smem + SM_ROWS + row * 8);
            float2 p1 = *(const float2*)(smem + SM_ROWS + (128 + row) * 8);
            float mu = (p0.x + p1.x) * (1.0f / 128.0f);
            float var = (p0.y + p1.y) * (1.0f / 128.0f) - mu * mu;
            float rs = rsqrtf(var + 1e-5f);
            int gn = nodeBase + row;
            if (gn < N_NODES) {
#pragma unroll
                for (int nt = 0; nt < 8; nt++) {
                    int j0 = warpN * 64 + nt * 8 + laneK2;
                    float z0 = acc[mt][nt][rh * 2 + 0];
                    float z1 = acc[mt][nt][rh * 2 + 1];
                    float2 o;
                    o.x = fmaxf((z0 - mu) * rs * sg[j0] + sbeta[j0], 0.f);
                    o.y = fmaxf((z1 - mu) * rs * sg[j0 + 1] + sbeta[j0 + 1], 0.f);
                    *(float2*)(out + (size_t)gn * 128 + j0) = o;
                }
            }
        }
}

extern "C" void kernel_launch(void* const* d_in, const int* in_sizes, int n_in,
                              void* d_out, int out_size) {
    const float* h     = (const float*)d_in[0];
    const float* dist  = (const float*)d_in[1];
    const float* W     = (const float*)d_in[2];
    const float* b     = (const float*)d_in[3];
    const float* gamma = (const float*)d_in[4];
    const float* beta  = (const float*)d_in[5];
    const int* src     = (const int*)d_in[6];
    const int* dst     = (const int*)d_in[7];
    const int* pos     = (const int*)d_in[8];
    float* out = (float*)d_out;

    cudaFuncSetAttribute(gemm_ln_kernel,
                         cudaFuncAttributeMaxDynamicSharedMemorySize, SMEM_GEMM);

    void* cntp = nullptr; cudaGetSymbolAddress(&cntp, g_cnt);
    cudaMemsetAsync(cntp, 0, (N_NODES + 1) * sizeof(int));

    weff_kernel<<<(D * KDIM + 255) / 256, 256>>>(W);

    fill_kernel<<<(E_EDGES + 255) / 256, 256>>>(dist, src, dst, pos);

    agg_kernel<<<(N_NODES * 32 + 255) / 256, 256>>>((const float4*)h);

    fixup_kernel<<<8, 256>>>((const float4*)h);

    gemm_ln_kernel<<<(N_NODES + 127) / 128, 256, SMEM_GEMM>>>(h, b, gamma, beta, out);
}

// round 8
// speedup vs baseline: 4.1379x; 1.2091x over previous
#include <cuda_runtime.h>
#include <cuda_bf16.h>

#define N_NODES 50000
#define N_PAD 50048
#define E_EDGES 800000
#define D 128
#define KDIM 512
#define CAP 96
#define OVF_CAP 4096

typedef unsigned long long u64;
typedef unsigned int u32;

// Scratch (allocation-free rule: __device__ globals)
// g_Xh/g_Xl: [node][512] split-bf16 X, 128B per 64-col chunk, 16B units
// pre-permuted by (node & 7) so GEMM smem fill is a straight copy.
__device__ __nv_bfloat16 g_Xh[(size_t)N_PAD * KDIM];
__device__ __nv_bfloat16 g_Xl[(size_t)N_PAD * KDIM];
__device__ __nv_bfloat16 g_Wh[8 * 8192];   // [chunk][n][64] pre-permuted
__device__ __nv_bfloat16 g_Wl[8 * 8192];
__device__ u64 g_rec[(size_t)N_NODES * CAP];
__device__ int g_cnt[N_NODES + 1];         // [N_NODES] = overflow count
__device__ int4 g_ovf[OVF_CAP];

// ---------------------------------------------------------------------------
// prep: zero counters + fold/split/swizzle W + split/swizzle h chunks 0-1.
// ---------------------------------------------------------------------------
#define PREP_H 1600000                 // 50000*32 float4 units of h
#define PREP_W (PREP_H + 65536)
#define PREP_END (PREP_W + 50001)

__global__ void prep_kernel(const float* __restrict__ h,
                            const float* __restrict__ W) {
    int i = blockIdx.x * blockDim.x + threadIdx.x;
    if (i < PREP_H) {
        int node = i >> 5;
        int j = i & 31;                     // float4 index within row
        float4 f = ((const float4*)h)[(size_t)node * 32 + j];
        float ff[4] = {f.x, f.y, f.z, f.w};
        u32 hw[2], lw[2];
#pragma unroll
        for (int q = 0; q < 2; q++) {
            __nv_bfloat16 h0 = __float2bfloat16(ff[2 * q]);
            __nv_bfloat16 h1 = __float2bfloat16(ff[2 * q + 1]);
            __nv_bfloat16 l0 = __float2bfloat16(ff[2 * q] - __bfloat162float(h0));
            __nv_bfloat16 l1 = __float2bfloat16(ff[2 * q + 1] - __bfloat162float(h1));
            hw[q] = (u32)__bfloat16_as_ushort(h0) | ((u32)__bfloat16_as_ushort(h1) << 16);
            lw[q] = (u32)__bfloat16_as_ushort(l0) | ((u32)__bfloat16_as_ushort(l1) << 16);
        }
        int chunk = j >> 4;
        int jj = j & 15;
        int u = jj >> 1, half = jj & 1;
        size_t db = (size_t)node * 1024 + chunk * 128 + ((u ^ (node & 7)) << 4) + half * 8;
        *(uint2*)((char*)g_Xh + db) = make_uint2(hw[0], hw[1]);
        *(uint2*)((char*)g_Xl + db) = make_uint2(lw[0], lw[1]);
    } else if (i < PREP_W) {
        int i2 = i - PREP_H;
        int n = i2 >> 9;
        int c = i2 & 511;
        float v = W[n * 640 + c];
        if (c >= 128 && c < 256) v += W[n * 640 + c + 384];
        __nv_bfloat16 hi = __float2bfloat16(v);
        __nv_bfloat16 lo = __float2bfloat16(v - __bfloat162float(hi));
        int chunk = c >> 6, kk = c & 63;
        int u = kk >> 3, sub = kk & 7;
        size_t db = (size_t)chunk * 16384 + n * 128 + ((u ^ (n & 7)) << 4) + sub * 2;
        *(__nv_bfloat16*)((char*)g_Wh + db) = hi;
        *(__nv_bfloat16*)((char*)g_Wl + db) = lo;
    } else if (i < PREP_END) {
        g_cnt[i - PREP_W] = 0;
    }
}

// ---------------------------------------------------------------------------
// Bucket contributing edges by dst. Record = (src | p<<16, f32 w) packed u64.
// ---------------------------------------------------------------------------
__global__ void fill_kernel(const float* __restrict__ dist,
                            const int* __restrict__ src,
                            const int* __restrict__ dst,
                            const int* __restrict__ pos) {
    int e = blockIdx.x * blockDim.x + threadIdx.x;
    if (e >= E_EDGES) return;
    int p = pos[e];
    if (p >= 3) return;
    int d = dst[e];
    int s = src[e];
    float w = dist[e];
    int slot = atomicAdd(&g_cnt[d], 1);
    if (slot < CAP) {
        unsigned lo = (unsigned)s | ((unsigned)p << 16);
        unsigned hi = __float_as_uint(w);
        g_rec[(size_t)d * CAP + slot] = (u64)lo | ((u64)hi << 32);
    } else {
        int o = atomicAdd(&g_cnt[N_NODES], 1);
        if (o < OVF_CAP) g_ovf[o] = make_int4(s, d, p, __float_as_int(w));
    }
}

// ---------------------------------------------------------------------------
// Aggregation: one warp per dst node; 3 direction channels in registers;
// overflow handled inline; output written as split-bf16 X chunks 2-7,
// pre-permuted for the GEMM's straight cp.async copy.
// ---------------------------------------------------------------------------
__global__ __launch_bounds__(256) void agg_kernel(const float4* __restrict__ h4) {
    int idx = blockIdx.x * blockDim.x + threadIdx.x;
    int d = idx >> 5;
    int lane = idx & 31;
    if (d >= N_NODES) return;
    int deg = g_cnt[d];
    float4 a[3];
#pragma unroll
    for (int p = 0; p < 3; p++) a[p] = make_float4(0.f, 0.f, 0.f, 0.f);

    const u64* rp = g_rec + (size_t)d * CAP;
    int nrec = deg > CAP ? CAP : deg;
#pragma unroll 4
    for (int i = 0; i < nrec; i++) {
        u64 rec = __ldg(rp + i);
        unsigned lo = (unsigned)rec;
        float w = __uint_as_float((unsigned)(rec >> 32));
        int s = lo & 0xFFFF;
        int p = lo >> 16;
        float4 hv = h4[(size_t)s * 32 + lane];
        if (p == 0)      { a[0].x += hv.x * w; a[0].y += hv.y * w; a[0].z += hv.z * w; a[0].w += hv.w * w; }
        else if (p == 1) { a[1].x += hv.x * w; a[1].y += hv.y * w; a[1].z += hv.z * w; a[1].w += hv.w * w; }
        else             { a[2].x += hv.x * w; a[2].y += hv.y * w; a[2].z += hv.z * w; a[2].w += hv.w * w; }
    }
    if (deg > CAP) {   // inline overflow fixup (normally zero iterations)
        int n = g_cnt[N_NODES];
        if (n > OVF_CAP) n = OVF_CAP;
        for (int i = 0; i < n; i++) {
            int4 r = g_ovf[i];
            if (r.y != d) continue;
            float w = __int_as_float(r.w);
            float4 hv = h4[(size_t)r.x * 32 + lane];
            int p = r.z;
            if (p == 0)      { a[0].x += hv.x * w; a[0].y += hv.y * w; a[0].z += hv.z * w; a[0].w += hv.w * w; }
            else if (p == 1) { a[1].x += hv.x * w; a[1].y += hv.y * w; a[1].z += hv.z * w; a[1].w += hv.w * w; }
            else             { a[2].x += hv.x * w; a[2].y += hv.y * w; a[2].z += hv.z * w; a[2].w += hv.w * w; }
        }
    }
    // split-bf16 store: direction p -> chunks 2+2p (+1 for lanes 16-31)
    int chunkBase = 2 + (lane >> 4);
    int u = (lane & 15) >> 1, half = lane & 1;
    size_t db0 = (size_t)d * 1024 + ((u ^ (d & 7)) << 4) + half * 8;
#pragma unroll
    for (int p = 0; p < 3; p++) {
        float ff[4] = {a[p].x, a[p].y, a[p].z, a[p].w};
        u32 hw[2], lw[2];
#pragma unroll
        for (int q = 0; q < 2; q++) {
            __nv_bfloat16 h0 = __float2bfloat16(ff[2 * q]);
            __nv_bfloat16 h1 = __float2bfloat16(ff[2 * q + 1]);
            __nv_bfloat16 l0 = __float2bfloat16(ff[2 * q] - __bfloat162float(h0));
            __nv_bfloat16 l1 = __float2bfloat16(ff[2 * q + 1] - __bfloat162float(h1));
            hw[q] = (u32)__bfloat16_as_ushort(h0) | ((u32)__bfloat16_as_ushort(h1) << 16);
            lw[q] = (u32)__bfloat16_as_ushort(l0) | ((u32)__bfloat16_as_ushort(l1) << 16);
        }
        size_t db = db0 + (chunkBase + 2 * p) * 128;
        *(uint2*)((char*)g_Xh + db) = make_uint2(hw[0], hw[1]);
        *(uint2*)((char*)g_Xl + db) = make_uint2(lw[0], lw[1]);
    }
}

// ---------------------------------------------------------------------------
// Split-bf16 mma.sync GEMM + bias + LayerNorm + ReLU.
// All tiles arrive via straight cp.async (pre-split, pre-swizzled in gmem).
// X double-buffered, B single-buffered. CTA 128x128, 8 warps 4(M)x2(N).
// ---------------------------------------------------------------------------
#define SM_BIAS 0
#define SM_GAMMA 512
#define SM_BETA 1024
#define SM_ROWS 1536
#define SM_X 3584                       // 2 bufs x (Xh 16K | Xl 16K)
#define SM_B (SM_X + 65536)             // Bh 16K | Bl 16K
#define SMEM_GEMM (SM_B + 32768)        // 101888 B

__device__ __forceinline__ void mma_bf16(float* c, u32 a0, u32 a1, u32 a2, u32 a3,
                                         u32 b0, u32 b1) {
    asm volatile(
        "mma.sync.aligned.m16n8k16.row.col.f32.bf16.bf16.f32 "
        "{%0,%1,%2,%3}, {%4,%5,%6,%7}, {%8,%9}, {%0,%1,%2,%3};"
        : "+f"(c[0]), "+f"(c[1]), "+f"(c[2]), "+f"(c[3])
        : "r"(a0), "r"(a1), "r"(a2), "r"(a3), "r"(b0), "r"(b1));
}
#define LDSM4(r0, r1, r2, r3, addr) \
    asm volatile("ldmatrix.sync.aligned.m8n8.x4.shared.b16 {%0,%1,%2,%3}, [%4];" \
                 : "=r"(r0), "=r"(r1), "=r"(r2), "=r"(r3) : "r"(addr))
#define CP16(dst, src) \
    asm volatile("cp.async.cg.shared.global [%0], [%1], 16;" :: "r"(dst), "l"(src))
#define CP_COMMIT() asm volatile("cp.async.commit_group;" ::: "memory")
#define CP_WAIT1() asm volatile("cp.async.wait_group 1;" ::: "memory")
#define CP_WAIT0() asm volatile("cp.async.wait_group 0;" ::: "memory")

__device__ __forceinline__ u32 smem_u32(const void* p) {
    u32 a;
    asm("{ .reg .u64 t; cvta.to.shared.u64 t, %1; cvt.u32.u64 %0, t; }"
        : "=r"(a) : "l"(p));
    return a;
}

__global__ __launch_bounds__(256, 2) void gemm_ln_kernel(
    const float* __restrict__ bias,
    const float* __restrict__ gamma,
    const float* __restrict__ beta,
    float* __restrict__ out) {

    extern __shared__ char smem[];
    const u32 sbase = smem_u32(smem);
    const int tid = threadIdx.x;
    const int lane = tid & 31;
    const int wid = tid >> 5;
    const int warpM = wid >> 1;
    const int warpN = wid & 1;
    const int nodeBase = blockIdx.x * 128;
    const int laneRow = lane >> 2;
    const int laneK2 = (lane & 3) * 2;
    const int lr = lane & 7;
    const int lg = lane >> 3;

    const int aRowB = warpM * 32 + (lg & 1) * 8 + lr;
    const int aUG = lg >> 1;
    const int aSw = aRowB & 7;
    const int bRowB = warpN * 64 + (lg >> 1) * 8 + lr;
    const int bUG = lg & 1;
    const int bSw = bRowB & 7;

    if (tid < 128) {
        *(float*)(smem + SM_BIAS + tid * 4) = bias[tid];
        *(float*)(smem + SM_GAMMA + tid * 4) = gamma[tid];
        *(float*)(smem + SM_BETA + tid * 4) = beta[tid];
    }

    float acc[2][8][4];
#pragma unroll
    for (int mt = 0; mt < 2; mt++)
#pragma unroll
        for (int nt = 0; nt < 8; nt++)
#pragma unroll
            for (int q = 0; q < 4; q++) acc[mt][nt][q] = 0.f;

    // straight-copy issuers
    const size_t xrowbase = (size_t)nodeBase * 1024;
    auto issue_X = [&](int c, int buf) {
        u32 db = sbase + SM_X + buf * 32768;
#pragma unroll
        for (int it = 0; it < 4; it++) {
            int u = tid + it * 256;          // 0..1023 16B units
            int row = u >> 3, un = u & 7;
            size_t so = xrowbase + (size_t)row * 1024 + c * 128 + un * 16;
            CP16(db + row * 128 + un * 16, (const char*)g_Xh + so);
            CP16(db + 16384 + row * 128 + un * 16, (const char*)g_Xl + so);
        }
    };
    auto issue_B = [&](int c) {
#pragma unroll
        for (int it = 0; it < 4; it++) {
            int u = tid + it * 256;
            size_t so = (size_t)c * 16384 + u * 16;
            CP16(sbase + SM_B + u * 16, (const char*)g_Wh + so);
            CP16(sbase + SM_B + 16384 + u * 16, (const char*)g_Wl + so);
        }
    };

    issue_X(0, 0);
    issue_B(0);
    CP_COMMIT();

    for (int c = 0; c < 8; c++) {
        if (c < 7) {
            issue_X(c + 1, (c + 1) & 1);
            CP_COMMIT();
            CP_WAIT1();
        } else {
            CP_WAIT0();
        }
        __syncthreads();

        const u32 xh = sbase + SM_X + (c & 1) * 32768;
        const u32 xl = xh + 16384;
        const u32 bh = sbase + SM_B;
        const u32 bl = bh + 16384;
#pragma unroll
        for (int ks = 0; ks < 4; ks++) {
            u32 ah[2][4], al[2][4], bf[8][2];
            const int aCol = ((2 * ks + aUG) ^ aSw) << 4;
            const int bCol = ((2 * ks + bUG) ^ bSw) << 4;
#pragma unroll
            for (int mt = 0; mt < 2; mt++) {
                u32 ro = (u32)((aRowB + mt * 16) * 128 + aCol);
                LDSM4(ah[mt][0], ah[mt][1], ah[mt][2], ah[mt][3], xh + ro);
            }
#pragma unroll
            for (int mt = 0; mt < 2; mt++) {
                u32 ro = (u32)((aRowB + mt * 16) * 128 + aCol);
                LDSM4(al[mt][0], al[mt][1], al[mt][2], al[mt][3], xl + ro);
            }
#pragma unroll
            for (int ntp = 0; ntp < 4; ntp++) {
                u32 ro = (u32)((bRowB + ntp * 16) * 128 + bCol);
                LDSM4(bf[2 * ntp][0], bf[2 * ntp][1],
                      bf[2 * ntp + 1][0], bf[2 * ntp + 1][1], bh + ro);
            }
#pragma unroll
            for (int mt = 0; mt < 2; mt++)
#pragma unroll
                for (int nt = 0; nt < 8; nt++)
                    mma_bf16(acc[mt][nt], ah[mt][0], ah[mt][1], ah[mt][2], ah[mt][3],
                             bf[nt][0], bf[nt][1]);
#pragma unroll
            for (int mt = 0; mt < 2; mt++)
#pragma unroll
                for (int nt = 0; nt < 8; nt++)
                    mma_bf16(acc[mt][nt], al[mt][0], al[mt][1], al[mt][2], al[mt][3],
                             bf[nt][0], bf[nt][1]);
#pragma unroll
            for (int ntp = 0; ntp < 4; ntp++) {
                u32 ro = (u32)((bRowB + ntp * 16) * 128 + bCol);
                LDSM4(bf[2 * ntp][0], bf[2 * ntp][1],
                      bf[2 * ntp + 1][0], bf[2 * ntp + 1][1], bl + ro);
            }
#pragma unroll
            for (int mt = 0; mt < 2; mt++)
#pragma unroll
                for (int nt = 0; nt < 8; nt++)
                    mma_bf16(acc[mt][nt], ah[mt][0], ah[mt][1], ah[mt][2], ah[mt][3],
                             bf[nt][0], bf[nt][1]);
        }
        __syncthreads();
        if (c < 7) {
            issue_B(c + 1);
            CP_COMMIT();
        }
    }

    // ---- Epilogue: bias + LN sums from fragments ----
    const float* sbias = (const float*)(smem + SM_BIAS);
    float s1[2][2], s2[2][2];
#pragma unroll
    for (int mt = 0; mt < 2; mt++) { s1[mt][0] = s1[mt][1] = s2[mt][0] = s2[mt][1] = 0.f; }
#pragma unroll
    for (int mt = 0; mt < 2; mt++)
#pragma unroll
        for (int nt = 0; nt < 8; nt++) {
            int j0 = warpN * 64 + nt * 8 + laneK2;
            float b0 = sbias[j0], b1 = sbias[j0 + 1];
            acc[mt][nt][0] += b0; acc[mt][nt][1] += b1;
            acc[mt][nt][2] += b0; acc[mt][nt][3] += b1;
            s1[mt][0] += acc[mt][nt][0] + acc[mt][nt][1];
            s2[mt][0] += acc[mt][nt][0] * acc[mt][nt][0] + acc[mt][nt][1] * acc[mt][nt][1];
            s1[mt][1] += acc[mt][nt][2] + acc[mt][nt][3];
            s2[mt][1] += acc[mt][nt][2] * acc[mt][nt][2] + acc[mt][nt][3] * acc[mt][nt][3];
        }
#pragma unroll
    for (int mt = 0; mt < 2; mt++)
#pragma unroll
        for (int rh = 0; rh < 2; rh++) {
            s1[mt][rh] += __shfl_xor_sync(0xFFFFFFFF, s1[mt][rh], 1);
            s1[mt][rh] += __shfl_xor_sync(0xFFFFFFFF, s1[mt][rh], 2);
            s2[mt][rh] += __shfl_xor_sync(0xFFFFFFFF, s2[mt][rh], 1);
            s2[mt][rh] += __shfl_xor_sync(0xFFFFFFFF, s2[mt][rh], 2);
        }
    if ((lane & 3) == 0) {
#pragma unroll
        for (int mt = 0; mt < 2; mt++)
#pragma unroll
            for (int rh = 0; rh < 2; rh++) {
                int row = warpM * 32 + mt * 16 + rh * 8 + laneRow;
                *(float2*)(smem + SM_ROWS + (warpN * 128 + row) * 8) =
                    make_float2(s1[mt][rh], s2[mt][rh]);
            }
    }
    __syncthreads();

    const float* sg = (const float*)(smem + SM_GAMMA);
    const float* sbeta = (const float*)(smem + SM_BETA);
#pragma unroll
    for (int mt = 0; mt < 2; mt++)
#pragma unroll
        for (int rh = 0; rh < 2; rh++) {
            int row = warpM * 32 + mt * 16 + rh * 8 + laneRow;
            float2 p0 = *(const float2*)(smem + SM_ROWS + row * 8);
            float2 p1 = *(const float2*)(smem + SM_ROWS + (128 + row) * 8);
            float mu = (p0.x + p1.x) * (1.0f / 128.0f);
            float var = (p0.y + p1.y) * (1.0f / 128.0f) - mu * mu;
            float rs = rsqrtf(var + 1e-5f);
            int gn = nodeBase + row;
            if (gn < N_NODES) {
#pragma unroll
                for (int nt = 0; nt < 8; nt++) {
                    int j0 = warpN * 64 + nt * 8 + laneK2;
                    float z0 = acc[mt][nt][rh * 2 + 0];
                    float z1 = acc[mt][nt][rh * 2 + 1];
                    float2 o;
                    o.x = fmaxf((z0 - mu) * rs * sg[j0] + sbeta[j0], 0.f);
                    o.y = fmaxf((z1 - mu) * rs * sg[j0 + 1] + sbeta[j0 + 1], 0.f);
                    *(float2*)(out + (size_t)gn * 128 + j0) = o;
                }
            }
        }
}

extern "C" void kernel_launch(void* const* d_in, const int* in_sizes, int n_in,
                              void* d_out, int out_size) {
    const float* h     = (const float*)d_in[0];
    const float* dist  = (const float*)d_in[1];
    const float* W     = (const float*)d_in[2];
    const float* b     = (const float*)d_in[3];
    const float* gamma = (const float*)d_in[4];
    const float* beta  = (const float*)d_in[5];
    const int* src     = (const int*)d_in[6];
    const int* dst     = (const int*)d_in[7];
    const int* pos     = (const int*)d_in[8];
    float* out = (float*)d_out;

    cudaFuncSetAttribute(gemm_ln_kernel,
                         cudaFuncAttributeMaxDynamicSharedMemorySize, SMEM_GEMM);

    prep_kernel<<<(PREP_END + 255) / 256, 256>>>(h, W);

    fill_kernel<<<(E_EDGES + 255) / 256, 256>>>(dist, src, dst, pos);

    agg_kernel<<<(N_NODES * 32 + 255) / 256, 256>>>((const float4*)h);

    gemm_ln_kernel<<<(N_NODES + 127) / 128, 256, SMEM_GEMM>>>(b, gamma, beta, out);
}